// round 3
// baseline (speedup 1.0000x reference)
#include <cuda_runtime.h>
#include <cstdint>

#define B_   128
#define S_   128
#define I_   300
#define H_   1024
#define G4_  4096
#define CC_  2

// ---------------- static scratch (no allocation allowed) ----------------
__device__ float d_G[(size_t)S_ * B_ * G4_];      // [s][b][4096] input-path gate preacts (+biases), 256MB
__device__ float d_hs[(size_t)(S_ + 1) * B_ * H_]; // h per step; slot 0 = h0 = 0
__device__ float d_c[B_ * H_];                     // cell state
__device__ float d_part[2][B_ * G4_];              // K-split partial sums for recurrent GEMM

// ---------------- helpers ----------------
__device__ __forceinline__ uint32_t f2tf(float x) {
    uint32_t u;
    asm("cvt.rna.tf32.f32 %0, %1;" : "=r"(u) : "f"(x));
    return u;
}

__device__ __forceinline__ void mma_tf32(float c[4], const uint32_t a[4], const uint32_t b[2]) {
    asm volatile(
        "mma.sync.aligned.m16n8k8.row.col.f32.tf32.tf32.f32 "
        "{%0,%1,%2,%3}, {%4,%5,%6,%7}, {%8,%9}, {%0,%1,%2,%3};\n"
        : "+f"(c[0]), "+f"(c[1]), "+f"(c[2]), "+f"(c[3])
        : "r"(a[0]), "r"(a[1]), "r"(a[2]), "r"(a[3]),
          "r"(b[0]), "r"(b[1]));
}

__device__ __forceinline__ float sigmoidf_(float x) {
    return 1.0f / (1.0f + __expf(-x));
}

// ---------------- init: zero h0 and c ----------------
__global__ void init_state() {
    int idx = blockIdx.x * 256 + threadIdx.x;
    if (idx < B_ * H_) {
        d_c[idx] = 0.0f;
        d_hs[idx] = 0.0f;   // slot 0
    }
}

// ---------------- input-path GEMM ----------------
// G[s][b][g] = sum_k embed_W[x[b][s]][k] * W_ih[g][k] + b_ih[g] + b_hh[g]
// blockIdx.x = s (BM = 128 = all batch rows for this s), blockIdx.y = n-tile (64 wide)
__global__ __launch_bounds__(256) void embed_gemm(
    const int* __restrict__ x, const float* __restrict__ embW,
    const float* __restrict__ W_ih, const float* __restrict__ b_ih,
    const float* __restrict__ b_hh)
{
    __shared__ uint32_t As[128][20];
    __shared__ uint32_t Bs[64][20];
    __shared__ int toks[128];

    const int tid = threadIdx.x;
    const int s   = blockIdx.x;
    const int n0  = blockIdx.y * 64;

    if (tid < 128) toks[tid] = x[tid * S_ + s];   // x[b][s]

    const int w    = tid >> 5, lane = tid & 31;
    const int wm   = w >> 1,   wn   = w & 1;      // warp grid 4x2
    const int gr   = lane >> 2, gc  = lane & 3;
    const int mw   = wm * 32,  nw   = wn * 32;

    const int arow = tid >> 1, akb = (tid & 1) * 8;
    const int brow = tid >> 2, bkb = (tid & 3) * 4;

    float acc[2][4][4];
#pragma unroll
    for (int mi = 0; mi < 2; mi++)
#pragma unroll
        for (int ni = 0; ni < 4; ni++)
#pragma unroll
            for (int q = 0; q < 4; q++) acc[mi][ni][q] = 0.0f;

    __syncthreads();  // toks ready

    for (int kt = 0; kt < 19; kt++) {            // ceil(300/16)
        const int k0 = kt * 16;
        {
            const float* er = embW + (size_t)toks[arow] * I_;
#pragma unroll
            for (int kk = 0; kk < 8; kk++) {
                int k = k0 + akb + kk;
                float v = (k < I_) ? er[k] : 0.0f;
                As[arow][akb + kk] = f2tf(v);
            }
        }
        {
            const float* wr = W_ih + (size_t)(n0 + brow) * I_;
#pragma unroll
            for (int kk = 0; kk < 4; kk++) {
                int k = k0 + bkb + kk;
                float v = (k < I_) ? wr[k] : 0.0f;
                Bs[brow][bkb + kk] = f2tf(v);
            }
        }
        __syncthreads();

#pragma unroll
        for (int ks = 0; ks < 2; ks++) {
            uint32_t a[2][4], b[4][2];
#pragma unroll
            for (int mi = 0; mi < 2; mi++) {
                a[mi][0] = As[mw + mi * 16 + gr][ks * 8 + gc];
                a[mi][1] = As[mw + mi * 16 + 8 + gr][ks * 8 + gc];
                a[mi][2] = As[mw + mi * 16 + gr][ks * 8 + 4 + gc];
                a[mi][3] = As[mw + mi * 16 + 8 + gr][ks * 8 + 4 + gc];
            }
#pragma unroll
            for (int ni = 0; ni < 4; ni++) {
                b[ni][0] = Bs[nw + ni * 8 + gr][ks * 8 + gc];
                b[ni][1] = Bs[nw + ni * 8 + gr][ks * 8 + 4 + gc];
            }
#pragma unroll
            for (int mi = 0; mi < 2; mi++)
#pragma unroll
                for (int ni = 0; ni < 4; ni++)
                    mma_tf32(acc[mi][ni], a[mi], b[ni]);
        }
        __syncthreads();
    }

    // epilogue: add biases, store G
#pragma unroll
    for (int mi = 0; mi < 2; mi++) {
        const int m0 = mw + mi * 16 + gr;
#pragma unroll
        for (int ni = 0; ni < 4; ni++) {
            const int n = n0 + nw + ni * 8 + gc * 2;
            const float bias0 = b_ih[n] + b_hh[n];
            const float bias1 = b_ih[n + 1] + b_hh[n + 1];
            size_t base0 = ((size_t)s * B_ + m0) * G4_ + n;
            size_t base1 = ((size_t)s * B_ + m0 + 8) * G4_ + n;
            d_G[base0]     = acc[mi][ni][0] + bias0;
            d_G[base0 + 1] = acc[mi][ni][1] + bias1;
            d_G[base1]     = acc[mi][ni][2] + bias0;
            d_G[base1 + 1] = acc[mi][ni][3] + bias1;
        }
    }
}

// ---------------- recurrent GEMM: partial[ks][b][g] = sum_{k in split} h[b][k]*W_hh[g][k]
// blockIdx.x = n-tile (64 wide, 64 tiles), blockIdx.y = k-split (0/1, 512 each)
__global__ __launch_bounds__(256) void rec_gemm(int t, const float* __restrict__ W_hh) {
    __shared__ uint32_t As[128][20];
    __shared__ uint32_t Bs[64][20];

    const int tid  = threadIdx.x;
    const int n0   = blockIdx.x * 64;
    const int ksp  = blockIdx.y;
    const int kofs = ksp * 512;
    const float* __restrict__ hprev = d_hs + (size_t)t * B_ * H_;

    const int w    = tid >> 5, lane = tid & 31;
    const int wm   = w >> 1,   wn   = w & 1;
    const int gr   = lane >> 2, gc  = lane & 3;
    const int mw   = wm * 32,  nw   = wn * 32;

    const int arow = tid >> 1, akb = (tid & 1) * 8;
    const int brow = tid >> 2, bkb = (tid & 3) * 4;

    float acc[2][4][4];
#pragma unroll
    for (int mi = 0; mi < 2; mi++)
#pragma unroll
        for (int ni = 0; ni < 4; ni++)
#pragma unroll
            for (int q = 0; q < 4; q++) acc[mi][ni][q] = 0.0f;

    for (int kt = 0; kt < 32; kt++) {            // 512 / 16
        const int k0 = kofs + kt * 16;
        {
            const float* hr = hprev + (size_t)arow * H_ + k0 + akb;
#pragma unroll
            for (int kk = 0; kk < 8; kk++)
                As[arow][akb + kk] = f2tf(hr[kk]);
        }
        {
            const float* wr = W_hh + (size_t)(n0 + brow) * H_ + k0 + bkb;
#pragma unroll
            for (int kk = 0; kk < 4; kk++)
                Bs[brow][bkb + kk] = f2tf(wr[kk]);
        }
        __syncthreads();

#pragma unroll
        for (int ks = 0; ks < 2; ks++) {
            uint32_t a[2][4], b[4][2];
#pragma unroll
            for (int mi = 0; mi < 2; mi++) {
                a[mi][0] = As[mw + mi * 16 + gr][ks * 8 + gc];
                a[mi][1] = As[mw + mi * 16 + 8 + gr][ks * 8 + gc];
                a[mi][2] = As[mw + mi * 16 + gr][ks * 8 + 4 + gc];
                a[mi][3] = As[mw + mi * 16 + 8 + gr][ks * 8 + 4 + gc];
            }
#pragma unroll
            for (int ni = 0; ni < 4; ni++) {
                b[ni][0] = Bs[nw + ni * 8 + gr][ks * 8 + gc];
                b[ni][1] = Bs[nw + ni * 8 + gr][ks * 8 + 4 + gc];
            }
#pragma unroll
            for (int mi = 0; mi < 2; mi++)
#pragma unroll
                for (int ni = 0; ni < 4; ni++)
                    mma_tf32(acc[mi][ni], a[mi], b[ni]);
        }
        __syncthreads();
    }

    float* __restrict__ P = d_part[ksp];
#pragma unroll
    for (int mi = 0; mi < 2; mi++) {
        const int m0 = mw + mi * 16 + gr;
#pragma unroll
        for (int ni = 0; ni < 4; ni++) {
            const int n = n0 + nw + ni * 8 + gc * 2;
            P[(size_t)m0 * G4_ + n]           = acc[mi][ni][0];
            P[(size_t)m0 * G4_ + n + 1]       = acc[mi][ni][1];
            P[(size_t)(m0 + 8) * G4_ + n]     = acc[mi][ni][2];
            P[(size_t)(m0 + 8) * G4_ + n + 1] = acc[mi][ni][3];
        }
    }
}

// ---------------- LSTM cell pointwise ----------------
__global__ __launch_bounds__(256) void lstm_cell(int t) {
    const int idx = blockIdx.x * 256 + threadIdx.x;   // 0 .. 131071
    const int b = idx >> 10;
    const int j = idx & 1023;

    const float* __restrict__ Gt = d_G + ((size_t)t * B_ + b) * G4_;
    const float* __restrict__ P0 = d_part[0] + (size_t)b * G4_;
    const float* __restrict__ P1 = d_part[1] + (size_t)b * G4_;

    const float ig = Gt[j]        + P0[j]        + P1[j];
    const float fg = Gt[j + 1024] + P0[j + 1024] + P1[j + 1024];
    const float gg = Gt[j + 2048] + P0[j + 2048] + P1[j + 2048];
    const float og = Gt[j + 3072] + P0[j + 3072] + P1[j + 3072];

    const float cold = d_c[idx];
    const float cn = sigmoidf_(fg) * cold + sigmoidf_(ig) * tanhf(gg);
    const float h  = sigmoidf_(og) * tanhf(cn);

    d_c[idx] = cn;
    d_hs[(size_t)(t + 1) * B_ * H_ + idx] = h;
}

// ---------------- output projection + length mask ----------------
// one warp per (b, s)
__global__ __launch_bounds__(256) void out_proj(
    const int* __restrict__ lengths, const float* __restrict__ linW,
    const float* __restrict__ linb, float* __restrict__ out)
{
    const int gw   = (blockIdx.x * 256 + threadIdx.x) >> 5;   // 0 .. 16383
    const int lane = threadIdx.x & 31;
    const int b = gw >> 7;
    const int s = gw & 127;

    const float* __restrict__ h = d_hs + ((size_t)(s + 1) * B_ + b) * H_;
    float s0 = 0.0f, s1 = 0.0f;
#pragma unroll 8
    for (int j = lane; j < H_; j += 32) {
        const float hv = h[j];
        s0 += hv * linW[j];
        s1 += hv * linW[H_ + j];
    }
#pragma unroll
    for (int o = 16; o > 0; o >>= 1) {
        s0 += __shfl_xor_sync(0xFFFFFFFFu, s0, o);
        s1 += __shfl_xor_sync(0xFFFFFFFFu, s1, o);
    }
    if (lane == 0) {
        float* orow = out + ((size_t)b * S_ + s) * CC_;
        if (s < lengths[b]) {
            orow[0] = s0 + linb[0];
            orow[1] = s1 + linb[1];
        } else {
            orow[0] = 1.0f;
            orow[1] = 0.0f;
        }
    }
}

// ---------------- launch ----------------
extern "C" void kernel_launch(void* const* d_in, const int* in_sizes, int n_in,
                              void* d_out, int out_size) {
    const int*   x       = (const int*)d_in[0];
    const int*   lengths = (const int*)d_in[1];
    const float* embW    = (const float*)d_in[2];
    const float* W_ih    = (const float*)d_in[3];
    const float* W_hh    = (const float*)d_in[4];
    const float* b_ih    = (const float*)d_in[5];
    const float* b_hh    = (const float*)d_in[6];
    const float* linW    = (const float*)d_in[7];
    const float* linb    = (const float*)d_in[8];
    float*       out     = (float*)d_out;

    init_state<<<512, 256>>>();
    embed_gemm<<<dim3(128, 64), 256>>>(x, embW, W_ih, b_ih, b_hh);
    for (int t = 0; t < S_; t++) {
        rec_gemm<<<dim3(64, 2), 256>>>(t, W_hh);
        lstm_cell<<<512, 256>>>(t);
    }
    out_proj<<<2048, 256>>>(lengths, linW, linb, out);
}